// round 15
// baseline (speedup 1.0000x reference)
#include <cuda_runtime.h>
#include <cuda_bf16.h>
#include <math.h>

// Problem constants
#define NB 4
#define NS 2048
#define ND 1024
#define NHD 64
#define NM (NB*NS)   // 8192

// ---------------- scratch (device globals; no allocation allowed) ----------
__device__ float g_Wqh[ND*NHD];
__device__ float g_Wkh[ND*NHD];
__device__ float g_Wvh[ND*NHD];
__device__ float g_Wored[NHD*ND];
__device__ __nv_bfloat16 g_Wqh_hi[ND*NHD], g_Wqh_lo[ND*NHD];
__device__ __nv_bfloat16 g_Wkh_hi[ND*NHD], g_Wkh_lo[ND*NHD];
__device__ __nv_bfloat16 g_Wvh_hi[ND*NHD], g_Wvh_lo[ND*NHD];
__device__ __nv_bfloat16 g_Wo_hi[NHD*ND],  g_Wo_lo[NHD*ND];
__device__ __nv_bfloat16 g_qh_hi[NM*NHD], g_qh_lo[NM*NHD];
__device__ __nv_bfloat16 g_kh_hi[NM*NHD], g_kh_lo[NM*NHD];
__device__ __nv_bfloat16 g_vh_hi[NM*NHD], g_vh_lo[NM*NHD];
__device__ float g_po[4][NM*NHD];
__device__ float g_pm[4][NM];
__device__ float g_pl[4][NM];
__device__ __nv_bfloat16 g_oh_hi[NM*NHD], g_oh_lo[NM*NHD];

// ---------------- helpers ---------------------------------------------------
__device__ __forceinline__ void bf16_split_pack(float x0, float x1,
                                                unsigned &hi, unsigned &lo) {
    __nv_bfloat16 h0 = __float2bfloat16_rn(x0);
    __nv_bfloat16 h1 = __float2bfloat16_rn(x1);
    __nv_bfloat16 l0 = __float2bfloat16_rn(x0 - __bfloat162float(h0));
    __nv_bfloat16 l1 = __float2bfloat16_rn(x1 - __bfloat162float(h1));
    hi = (unsigned)__bfloat16_as_ushort(h0) | ((unsigned)__bfloat16_as_ushort(h1) << 16);
    lo = (unsigned)__bfloat16_as_ushort(l0) | ((unsigned)__bfloat16_as_ushort(l1) << 16);
}
__device__ __forceinline__ void ldsm4(unsigned r[4], unsigned addr) {
    asm volatile("ldmatrix.sync.aligned.m8n8.x4.shared.b16 {%0,%1,%2,%3}, [%4];"
                 : "=r"(r[0]), "=r"(r[1]), "=r"(r[2]), "=r"(r[3]) : "r"(addr));
}
__device__ __forceinline__ void ldsm4t(unsigned r[4], unsigned addr) {
    asm volatile("ldmatrix.sync.aligned.m8n8.x4.trans.shared.b16 {%0,%1,%2,%3}, [%4];"
                 : "=r"(r[0]), "=r"(r[1]), "=r"(r[2]), "=r"(r[3]) : "r"(addr));
}
__device__ __forceinline__ void mma_bf16(float c[4], const unsigned a[4],
                                         unsigned b0, unsigned b1) {
    asm volatile(
        "mma.sync.aligned.m16n8k16.row.col.f32.bf16.bf16.f32 "
        "{%0,%1,%2,%3},{%4,%5,%6,%7},{%8,%9},{%0,%1,%2,%3};"
        : "+f"(c[0]), "+f"(c[1]), "+f"(c[2]), "+f"(c[3])
        : "r"(a[0]), "r"(a[1]), "r"(a[2]), "r"(a[3]), "r"(b0), "r"(b1));
}
__device__ __forceinline__ void cpa16(unsigned dst, const void* src) {
    asm volatile("cp.async.cg.shared.global [%0], [%1], 16;" :: "r"(dst), "l"(src));
}
#define CP_COMMIT asm volatile("cp.async.commit_group;")
#define CP_WAIT0  asm volatile("cp.async.wait_group 0;")
#define CP_WAIT1  asm volatile("cp.async.wait_group 1;")

// ---------------- zero + wored fused (R11) ----------------------------------
__global__ void prep0_kernel(const float* __restrict__ Wo) {
    if (blockIdx.x < 64) {
        int h = blockIdx.x;
        for (int e = threadIdx.x; e < ND; e += blockDim.x) {
            float s = 0.f;
            #pragma unroll
            for (int j = 0; j < 16; j++) s += Wo[(size_t)(j*NHD + h)*ND + e];
            g_Wored[h*ND + e] = s;
        }
    } else {
        int zb = blockIdx.x - 64;
        int base = zb * 2048;
        #pragma unroll
        for (int p = 0; p < 8; p++) {
            int i = base + threadIdx.x + p*256;
            if (i < 65536)        g_Wqh[i] = 0.f;
            else if (i < 131072)  g_Wkh[i - 65536] = 0.f;
            else                  g_Wvh[i - 131072] = 0.f;
        }
    }
}
__global__ void wsplit_kernel() {
    int m = blockIdx.y;
    const float* src = (m==0)?g_Wqh:(m==1)?g_Wkh:(m==2)?g_Wvh:g_Wored;
    unsigned* hi = (unsigned*)((m==0)?g_Wqh_hi:(m==1)?g_Wkh_hi:(m==2)?g_Wvh_hi:g_Wo_hi);
    unsigned* lo = (unsigned*)((m==0)?g_Wqh_lo:(m==1)?g_Wkh_lo:(m==2)?g_Wvh_lo:g_Wo_lo);
    int i = blockIdx.x*blockDim.x + threadIdx.x;
    float2 v = *(const float2*)(src + 2*i);
    unsigned h, l;
    bf16_split_pack(v.x, v.y, h, l);
    hi[i] = h; lo[i] = l;
}

// ---------------- combine (R4-exact): Wxh = Wx @ wx_h, split-K(8) atomic ----
#define G_SM_A_HI 0
#define G_SM_A_LO 5120
#define G_SM_B_HI 10240
#define G_SM_B_LO 14848
__global__ void __launch_bounds__(256) combine_kernel(
    const float* __restrict__ Wq, const float* __restrict__ Wk, const float* __restrict__ Wv,
    const float* __restrict__ wqh, const float* __restrict__ wkh, const float* __restrict__ wvh)
{
    int z = blockIdx.z;
    int which = z >> 3, chunk = z & 7;
    const float* A  = (which==0) ? Wq  : (which==1) ? Wk  : Wv;
    const float* Bm = (which==0) ? wqh : (which==1) ? wkh : wvh;
    float*       C  = (which==0) ? g_Wqh : (which==1) ? g_Wkh : g_Wvh;
    int m0 = blockIdx.x*64, kStart = chunk*128;

    __shared__ __align__(16) unsigned char sm[19456];
    unsigned sbase = (unsigned)__cvta_generic_to_shared(sm);
    int tid = threadIdx.x, lane = tid & 31, wid = tid >> 5;
    int wm = wid >> 1, wn = wid & 1;
    int lRow = lane & 15, lHi = (lane >> 4) << 3;

    float c[4][4] = {};
    float4 aReg[2], bReg[2];
    #pragma unroll
    for (int p = 0; p < 2; p++) {
        int idx = tid + p*256;
        aReg[p] = *(const float4*)(A + (size_t)(m0 + (idx>>3))*ND + kStart + (idx&7)*4);
        bReg[p] = *(const float4*)(Bm + (size_t)(kStart + (idx>>4))*NHD + (idx&15)*4);
    }
    for (int kb = 0; kb < 128; kb += 32) {
        #pragma unroll
        for (int p = 0; p < 2; p++) {
            int idx = tid + p*256;
            {   int r = idx>>3, c4 = idx&7;
                unsigned h01,l01,h23,l23;
                bf16_split_pack(aReg[p].x, aReg[p].y, h01, l01);
                bf16_split_pack(aReg[p].z, aReg[p].w, h23, l23);
                *(uint2*)(sm + G_SM_A_HI + r*80 + c4*8) = make_uint2(h01,h23);
                *(uint2*)(sm + G_SM_A_LO + r*80 + c4*8) = make_uint2(l01,l23);
            }
            {   int r = idx>>4, c4 = idx&15;
                unsigned h01,l01,h23,l23;
                bf16_split_pack(bReg[p].x, bReg[p].y, h01, l01);
                bf16_split_pack(bReg[p].z, bReg[p].w, h23, l23);
                *(uint2*)(sm + G_SM_B_HI + r*144 + c4*8) = make_uint2(h01,h23);
                *(uint2*)(sm + G_SM_B_LO + r*144 + c4*8) = make_uint2(l01,l23);
            }
        }
        __syncthreads();
        if (kb + 32 < 128) {
            int k0 = kStart + kb + 32;
            #pragma unroll
            for (int p = 0; p < 2; p++) {
                int idx = tid + p*256;
                aReg[p] = *(const float4*)(A + (size_t)(m0 + (idx>>3))*ND + k0 + (idx&7)*4);
                bReg[p] = *(const float4*)(Bm + (size_t)(k0 + (idx>>4))*NHD + (idx&15)*4);
            }
        }
        #pragma unroll
        for (int ks = 0; ks < 32; ks += 16) {
            unsigned ah[4], al[4], bh[2][4], bl[2][4];
            unsigned offA = sbase + G_SM_A_HI + (unsigned)((wm*16 + lRow)*80 + (ks + lHi)*2);
            ldsm4(ah, offA);
            ldsm4(al, offA + (G_SM_A_LO - G_SM_A_HI));
            #pragma unroll
            for (int np = 0; np < 2; np++) {
                unsigned offB = sbase + G_SM_B_HI + (unsigned)((ks + lRow)*144 + (wn*32 + np*16 + lHi)*2);
                ldsm4t(bh[np], offB);
                ldsm4t(bl[np], offB + (G_SM_B_LO - G_SM_B_HI));
            }
            #pragma unroll
            for (int nt = 0; nt < 4; nt++) {
                unsigned b0h = bh[nt>>1][(nt&1)*2], b1h = bh[nt>>1][(nt&1)*2+1];
                unsigned b0l = bl[nt>>1][(nt&1)*2], b1l = bl[nt>>1][(nt&1)*2+1];
                mma_bf16(c[nt], ah, b0h, b1h);
                mma_bf16(c[nt], ah, b0l, b1l);
                mma_bf16(c[nt], al, b0h, b1h);
            }
        }
        __syncthreads();
    }
    int rowL = m0 + wm*16 + (lane>>2);
    #pragma unroll
    for (int nt = 0; nt < 4; nt++) {
        int col = wn*32 + nt*8 + (lane&3)*2;
        atomicAdd(&C[(size_t)rowL*NHD+col],       c[nt][0]);
        atomicAdd(&C[(size_t)rowL*NHD+col+1],     c[nt][1]);
        atomicAdd(&C[(size_t)(rowL+8)*NHD+col],   c[nt][2]);
        atomicAdd(&C[(size_t)(rowL+8)*NHD+col+1], c[nt][3]);
    }
}

// ---------------- proj v7: BK=64, 2-stage B ring; now 4 CTAs/SM -------------
// smem (dynamic 55296): A hi @0 (64x144B=9216), A lo @9216,
// B stage s @18432+s*18432 (hi +0, lo +9216).
#define P_A_HI 0
#define P_A_LO 9216
#define P_BST(s) (18432 + (s)*18432)
#define P_SMEM  55296
__global__ void __launch_bounds__(256, 4) proj_kernel(
    const float* __restrict__ q, const float* __restrict__ k, const float* __restrict__ v,
    const float* __restrict__ bq, const float* __restrict__ bk, const float* __restrict__ bv)
{
    int which = blockIdx.z;
    const float* A    = (which==0) ? q     : (which==1) ? k     : v;
    const __nv_bfloat16* Whi = (which==0) ? g_Wqh_hi : (which==1) ? g_Wkh_hi : g_Wvh_hi;
    const __nv_bfloat16* Wlo = (which==0) ? g_Wqh_lo : (which==1) ? g_Wkh_lo : g_Wvh_lo;
    const float* bias = (which==0) ? bq    : (which==1) ? bk    : bv;
    __nv_bfloat16* Chi = (which==0) ? g_qh_hi : (which==1) ? g_kh_hi : g_vh_hi;
    __nv_bfloat16* Clo = (which==0) ? g_qh_lo : (which==1) ? g_kh_lo : g_vh_lo;

    extern __shared__ __align__(16) unsigned char sm[];
    unsigned sbase = (unsigned)__cvta_generic_to_shared(sm);
    int tid = threadIdx.x, lane = tid & 31, wid = tid >> 5;
    int wm = wid >> 1, wn = wid & 1;
    int lRow = lane & 15, lHi = (lane >> 4) << 3;
    int m0 = blockIdx.x*64;

    auto cpB = [&](int kt, int slot) {
        #pragma unroll
        for (int p = 0; p < 4; p++) {
            int idx = tid + p*256;                  // 0..1023
            int pl = idx >> 9, rr = (idx >> 3) & 63, ch = idx & 7;
            const __nv_bfloat16* src = pl ? Wlo : Whi;
            cpa16(sbase + (unsigned)(P_BST(slot) + pl*9216 + rr*144 + ch*16),
                  src + (size_t)(kt*64 + rr)*NHD + ch*8);
        }
    };

    float c[4][4] = {};
    float4 aReg[4];
    cpB(0, 0); CP_COMMIT;
    #pragma unroll
    for (int p = 0; p < 4; p++) {
        int idx = tid + p*256;
        aReg[p] = *(const float4*)(A + (size_t)(m0 + (idx>>4))*ND + (idx&15)*4);
    }

    for (int it = 0; it < 16; it++) {
        int st = it & 1;
        __syncthreads();
        #pragma unroll
        for (int p = 0; p < 4; p++) {
            int idx = tid + p*256;
            int r = idx>>4, ch = idx&15;
            unsigned h01,l01,h23,l23;
            bf16_split_pack(aReg[p].x, aReg[p].y, h01, l01);
            bf16_split_pack(aReg[p].z, aReg[p].w, h23, l23);
            *(uint2*)(sm + P_A_HI + r*144 + ch*8) = make_uint2(h01,h23);
            *(uint2*)(sm + P_A_LO + r*144 + ch*8) = make_uint2(l01,l23);
        }
        bool hasNext = (it + 1 < 16);
        if (hasNext) cpB(it + 1, st^1);
        CP_COMMIT;
        if (hasNext) {
            int k0 = (it + 1) * 64;
            #pragma unroll
            for (int p = 0; p < 4; p++) {
                int idx = tid + p*256;
                aReg[p] = *(const float4*)(A + (size_t)(m0 + (idx>>4))*ND + k0 + (idx&15)*4);
            }
        }
        CP_WAIT1;
        __syncthreads();
        unsigned pb = sbase + (unsigned)P_BST(st);
        #pragma unroll
        for (int ks = 0; ks < 64; ks += 16) {
            unsigned ah[4], al[4], bh[2][4], bl[2][4];
            unsigned offA = sbase + P_A_HI + (unsigned)((wm*16 + lRow)*144 + (ks + lHi)*2);
            ldsm4(ah, offA);
            ldsm4(al, offA + (P_A_LO - P_A_HI));
            #pragma unroll
            for (int np = 0; np < 2; np++) {
                unsigned offB = pb + (unsigned)((ks + lRow)*144 + (wn*32 + np*16 + lHi)*2);
                ldsm4t(bh[np], offB);
                ldsm4t(bl[np], offB + 9216);
            }
            #pragma unroll
            for (int nt = 0; nt < 4; nt++) {
                unsigned b0h = bh[nt>>1][(nt&1)*2], b1h = bh[nt>>1][(nt&1)*2+1];
                unsigned b0l = bl[nt>>1][(nt&1)*2], b1l = bl[nt>>1][(nt&1)*2+1];
                mma_bf16(c[nt], ah, b0h, b1h);
                mma_bf16(c[nt], ah, b0l, b1l);
                mma_bf16(c[nt], al, b0h, b1h);
            }
        }
    }
    int rowL = m0 + wm*16 + (lane>>2);
    #pragma unroll
    for (int nt = 0; nt < 4; nt++) {
        int col = wn*32 + nt*8 + (lane&3)*2;
        float v0 = c[nt][0] + bias[col],   v1 = c[nt][1] + bias[col+1];
        float v2 = c[nt][2] + bias[col],   v3 = c[nt][3] + bias[col+1];
        unsigned h01,l01,h23,l23;
        bf16_split_pack(v0,v1,h01,l01);
        bf16_split_pack(v2,v3,h23,l23);
        *(unsigned*)(Chi + (size_t)rowL*NHD + col)     = h01;
        *(unsigned*)(Clo + (size_t)rowL*NHD + col)     = l01;
        *(unsigned*)(Chi + (size_t)(rowL+8)*NHD + col) = h23;
        *(unsigned*)(Clo + (size_t)(rowL+8)*NHD + col) = l23;
    }
}

// ---------------- attention: BM=64, BN=32, balanced 4-way split-KV (R11) ----
#define AQ_HI 0
#define AQ_LO 8192
#define AST   16384
#define ASTSZ 16384

__device__ __forceinline__ void attn_load_stage(unsigned sbst, size_t kvbase, int tid) {
    #pragma unroll
    for (int p = 0; p < 2; p++) {
        int idx = tid + p*128;
        int r = idx >> 3, c = idx & 7;
        unsigned sw = (unsigned)(r*128 + ((c ^ (r & 7)) << 4));
        size_t g = kvbase + (size_t)r*NHD + c*8;
        cpa16(sbst + 0     + sw, g_kh_hi + g);
        cpa16(sbst + 4096  + sw, g_kh_lo + g);
        cpa16(sbst + 8192  + sw, g_vh_hi + g);
        cpa16(sbst + 12288 + sw, g_vh_lo + g);
    }
}

__global__ void __launch_bounds__(128) attn_kernel() {
    __shared__ __align__(16) unsigned char sm[49152];
    unsigned sb = (unsigned)__cvta_generic_to_shared(sm);
    int tid = threadIdx.x, lane = tid & 31, wid = tid >> 5;
    int qb = blockIdx.x, b = blockIdx.y, split = blockIdx.z;
    size_t base = (size_t)b * NS * NHD;
    int r0 = qb * 64;
    int T = 2*qb + 2;
    int jt0 = (split*T) >> 2;
    int jt1 = ((split+1)*T) >> 2;

    #pragma unroll
    for (int p = 0; p < 4; p++) {
        int idx = tid + p*128;
        int r = idx >> 3, c = idx & 7;
        unsigned sw = (unsigned)(r*128 + ((c ^ (r & 7)) << 4));
        size_t g = base + (size_t)(r0 + r)*NHD + c*8;
        cpa16(sb + AQ_HI + sw, g_qh_hi + g);
        cpa16(sb + AQ_LO + sw, g_qh_lo + g);
    }
    CP_COMMIT;
    if (jt0 < jt1)
        attn_load_stage(sb + AST + (unsigned)((jt0 & 1) * ASTSZ),
                        base + (size_t)jt0*32*NHD, tid);
    CP_COMMIT;
    CP_WAIT1;
    __syncthreads();

    unsigned qh_f[4][4], ql_f[4][4];
    {
        int row = wid*16 + (lane & 15);
        #pragma unroll
        for (int c = 0; c < 4; c++) {
            int ch = 2*c + (lane >> 4);
            unsigned addr = sb + AQ_HI + (unsigned)(row*128 + ((ch ^ (row & 7)) << 4));
            ldsm4(qh_f[c], addr);
            ldsm4(ql_f[c], addr + (AQ_LO - AQ_HI));
        }
    }

    float o[8][4] = {};
    float m0r = -1e30f, m1r = -1e30f, l0r = 0.f, l1r = 0.f;
    const float c1 = 0.125f * 1.4426950408889634f;

    for (int jt = jt0; jt < jt1; jt++) {
        unsigned cur = sb + AST + (unsigned)((jt & 1) * ASTSZ);
        if (jt + 1 < jt1)
            attn_load_stage(sb + AST + (unsigned)(((jt+1) & 1) * ASTSZ),
                            base + (size_t)(jt+1)*32*NHD, tid);
        CP_COMMIT;
        CP_WAIT1;
        __syncthreads();

        float s[4][4] = {};
        #pragma unroll
        for (int c = 0; c < 4; c++) {
            int ch = 2*c + ((lane >> 3) & 1);
            int keyr = ((lane >> 4) << 3) + (lane & 7);
            unsigned a0 = cur + (unsigned)(keyr*128 + ((ch ^ (keyr & 7)) << 4));
            unsigned a1 = a0 + 16*128;
            unsigned kh0[4], kh1[4], kl0[4], kl1[4];
            ldsm4(kh0, a0); ldsm4(kh1, a1);
            ldsm4(kl0, a0 + 4096); ldsm4(kl1, a1 + 4096);
            mma_bf16(s[0], qh_f[c], kh0[0], kh0[1]);
            mma_bf16(s[0], qh_f[c], kl0[0], kl0[1]);
            mma_bf16(s[0], ql_f[c], kh0[0], kh0[1]);
            mma_bf16(s[1], qh_f[c], kh0[2], kh0[3]);
            mma_bf16(s[1], qh_f[c], kl0[2], kl0[3]);
            mma_bf16(s[1], ql_f[c], kh0[2], kh0[3]);
            mma_bf16(s[2], qh_f[c], kh1[0], kh1[1]);
            mma_bf16(s[2], qh_f[c], kl1[0], kl1[1]);
            mma_bf16(s[2], ql_f[c], kh1[0], kh1[1]);
            mma_bf16(s[3], qh_f[c], kh1[2], kh1[3]);
            mma_bf16(s[3], qh_f[c], kl1[2], kl1[3]);
            mma_bf16(s[3], ql_f[c], kh1[2], kh1[3]);
        }

        bool dom = (jt >= 2*qb);
        int rgl = r0 + wid*16 + (lane >> 2);
        #pragma unroll
        for (int f = 0; f < 4; f++) {
            int kg = jt*32 + f*8 + (lane & 3)*2;
            #pragma unroll
            for (int e = 0; e < 4; e++) {
                float t = s[f][e] * c1;
                if (dom && (kg + (e & 1)) > (rgl + ((e >= 2) ? 8 : 0))) t = -1e30f;
                s[f][e] = t;
            }
        }

        float mx0 = -1e30f, mx1 = -1e30f;
        #pragma unroll
        for (int f = 0; f < 4; f++) {
            mx0 = fmaxf(mx0, fmaxf(s[f][0], s[f][1]));
            mx1 = fmaxf(mx1, fmaxf(s[f][2], s[f][3]));
        }
        mx0 = fmaxf(mx0, __shfl_xor_sync(0xffffffffu, mx0, 1));
        mx0 = fmaxf(mx0, __shfl_xor_sync(0xffffffffu, mx0, 2));
        mx1 = fmaxf(mx1, __shfl_xor_sync(0xffffffffu, mx1, 1));
        mx1 = fmaxf(mx1, __shfl_xor_sync(0xffffffffu, mx1, 2));
        float mn0 = fmaxf(m0r, mx0), mn1 = fmaxf(m1r, mx1);
        float al0 = exp2f(m0r - mn0), al1 = exp2f(m1r - mn1);
        m0r = mn0; m1r = mn1;
        float rs0 = 0.f, rs1 = 0.f;
        #pragma unroll
        for (int f = 0; f < 4; f++) {
            s[f][0] = exp2f(s[f][0] - mn0);
            s[f][1] = exp2f(s[f][1] - mn0);
            s[f][2] = exp2f(s[f][2] - mn1);
            s[f][3] = exp2f(s[f][3] - mn1);
            rs0 += s[f][0] + s[f][1];
            rs1 += s[f][2] + s[f][3];
        }
        rs0 += __shfl_xor_sync(0xffffffffu, rs0, 1);
        rs0 += __shfl_xor_sync(0xffffffffu, rs0, 2);
        rs1 += __shfl_xor_sync(0xffffffffu, rs1, 1);
        rs1 += __shfl_xor_sync(0xffffffffu, rs1, 2);
        l0r = l0r*al0 + rs0;
        l1r = l1r*al1 + rs1;
        #pragma unroll
        for (int f = 0; f < 8; f++) {
            o[f][0] *= al0; o[f][1] *= al0;
            o[f][2] *= al1; o[f][3] *= al1;
        }

        #pragma unroll
        for (int ka = 0; ka < 2; ka++) {
            unsigned ph[4], pl[4];
            bf16_split_pack(s[2*ka][0],   s[2*ka][1],   ph[0], pl[0]);
            bf16_split_pack(s[2*ka][2],   s[2*ka][3],   ph[1], pl[1]);
            bf16_split_pack(s[2*ka+1][0], s[2*ka+1][1], ph[2], pl[2]);
            bf16_split_pack(s[2*ka+1][2], s[2*ka+1][3], ph[3], pl[3]);
            #pragma unroll
            for (int fp = 0; fp < 4; fp++) {
                int ch = 2*fp + (lane >> 4);
                int kvr = ka*16 + (lane & 15);
                unsigned av = cur + 8192 + (unsigned)(kvr*128 + ((ch ^ (kvr & 7)) << 4));
                unsigned vh[4], vl[4];
                ldsm4t(vh, av); ldsm4t(vl, av + 4096);
                mma_bf16(o[2*fp],   ph, vh[0], vh[1]);
                mma_bf16(o[2*fp],   pl, vh[0], vh[1]);
                mma_bf16(o[2*fp],   ph, vl[0], vl[1]);
                mma_bf16(o[2*fp+1], ph, vh[2], vh[3]);
                mma_bf16(o[2*fp+1], pl, vh[2], vh[3]);
                mma_bf16(o[2*fp+1], ph, vl[2], vl[3]);
            }
        }
        __syncthreads();
    }

    int rowg = r0 + wid*16 + (lane >> 2);
    size_t rb = (size_t)b*NS + rowg;
    #pragma unroll
    for (int f = 0; f < 8; f++) {
        int hd = f*8 + (lane & 3)*2;
        *(float2*)(g_po[split] + rb*NHD + hd)     = make_float2(o[f][0], o[f][1]);
        *(float2*)(g_po[split] + (rb+8)*NHD + hd) = make_float2(o[f][2], o[f][3]);
    }
    if ((lane & 3) == 0) {
        g_pm[split][rb]   = m0r;  g_pl[split][rb]   = l0r;
        g_pm[split][rb+8] = m1r;  g_pl[split][rb+8] = l1r;
    }
}

// ---------------- merge 4 split-KV partials (R11) ---------------------------
__global__ void merge_kernel() {
    int idx = blockIdx.x*blockDim.x + threadIdx.x;
    int row = idx >> 5;
    int cp  = (idx & 31)*2;
    float m0 = g_pm[0][row], m1 = g_pm[1][row];
    float m2 = g_pm[2][row], m3 = g_pm[3][row];
    float M = fmaxf(fmaxf(m0, m1), fmaxf(m2, m3));
    float e0 = exp2f(m0 - M), e1 = exp2f(m1 - M);
    float e2 = exp2f(m2 - M), e3 = exp2f(m3 - M);
    float inv = 1.f / (g_pl[0][row]*e0 + g_pl[1][row]*e1
                     + g_pl[2][row]*e2 + g_pl[3][row]*e3);
    float2 a0 = *(const float2*)(g_po[0] + (size_t)row*NHD + cp);
    float2 a1 = *(const float2*)(g_po[1] + (size_t)row*NHD + cp);
    float2 a2 = *(const float2*)(g_po[2] + (size_t)row*NHD + cp);
    float2 a3 = *(const float2*)(g_po[3] + (size_t)row*NHD + cp);
    float x0 = (a0.x*e0 + a1.x*e1 + a2.x*e2 + a3.x*e3)*inv;
    float x1 = (a0.y*e0 + a1.y*e1 + a2.y*e2 + a3.y*e3)*inv;
    unsigned h, l;
    bf16_split_pack(x0, x1, h, l);
    *(unsigned*)(g_oh_hi + (size_t)row*NHD + cp) = h;
    *(unsigned*)(g_oh_lo + (size_t)row*NHD + cp) = l;
}

// ---------------- outgemm (R4-exact) ----------------------------------------
#define O_A_HI 0
#define O_A_LO 9216
#define O_B_HI 18432
#define O_B_LO 27648
__global__ void __launch_bounds__(256) outgemm_kernel(float* __restrict__ out) {
    __shared__ __align__(16) unsigned char sm[36864];
    unsigned sbase = (unsigned)__cvta_generic_to_shared(sm);
    int tid = threadIdx.x, lane = tid & 31, wid = tid >> 5;
    int wm = wid >> 1, wn = wid & 1;
    int lRow = lane & 15, lHi = (lane >> 4) << 3;
    int m0 = blockIdx.x*64, n0 = blockIdx.y*64;

    #pragma unroll
    for (int p = 0; p < 4; p++) {
        int idx = tid + p*256;
        int pl = (idx >> 9) & 1, r = (idx >> 3) & 63, ch = idx & 7;
        if (idx < 1024) {
            const __nv_bfloat16* srcA = pl ? g_oh_lo : g_oh_hi;
            cpa16(sbase + O_A_HI + pl*9216 + r*144 + ch*16, srcA + (size_t)(m0 + r)*NHD + ch*8);
        }
    }
    #pragma unroll
    for (int p = 0; p < 4; p++) {
        int idx = tid + p*256;
        int pl = (idx >> 9) & 1, r = (idx >> 3) & 63, ch = idx & 7;
        const __nv_bfloat16* srcB = pl ? g_Wo_lo : g_Wo_hi;
        cpa16(sbase + O_B_HI + pl*9216 + r*144 + ch*16, srcB + (size_t)r*ND + n0 + ch*8);
    }
    CP_COMMIT;
    CP_WAIT0;
    __syncthreads();

    float c[4][4] = {};
    #pragma unroll
    for (int ks = 0; ks < 4; ks++) {
        unsigned ah[4], al[4], bh[2][4], bl[2][4];
        unsigned offA = sbase + O_A_HI + (unsigned)((wm*16 + lRow)*144 + (ks*16 + lHi)*2);
        ldsm4(ah, offA);
        ldsm4(al, offA + 9216);
        #pragma unroll
        for (int np = 0; np < 2; np++) {
            unsigned offB = sbase + O_B_HI + (unsigned)((ks*16 + lRow)*144 + (wn*32 + np*16 + lHi)*2);
            ldsm4t(bh[np], offB);
            ldsm4t(bl[np], offB + 9216);
        }
        #pragma unroll
        for (int nt = 0; nt < 4; nt++) {
            unsigned b0h = bh[nt>>1][(nt&1)*2], b1h = bh[nt>>1][(nt&1)*2+1];
            unsigned b0l = bl[nt>>1][(nt&1)*2], b1l = bl[nt>>1][(nt&1)*2+1];
            mma_bf16(c[nt], ah, b0h, b1h);
            mma_bf16(c[nt], ah, b0l, b1l);
            mma_bf16(c[nt], al, b0h, b1h);
        }
    }
    int rowL = m0 + wm*16 + (lane>>2);
    #pragma unroll
    for (int nt = 0; nt < 4; nt++) {
        int col = n0 + wn*32 + nt*8 + (lane&3)*2;
        *(float2*)(out + (size_t)rowL*ND + col)     = make_float2(c[nt][0], c[nt][1]);
        *(float2*)(out + (size_t)(rowL+8)*ND + col) = make_float2(c[nt][2], c[nt][3]);
    }
}

// ---------------- launch ----------------------------------------------------
extern "C" void kernel_launch(void* const* d_in, const int* in_sizes, int n_in,
                              void* d_out, int out_size) {
    const float* query = (const float*)d_in[0];
    const float* key   = (const float*)d_in[1];
    const float* value = (const float*)d_in[2];
    // d_in[3] = mask (causal, reconstructed analytically — unused)
    const float* Wq   = (const float*)d_in[4];
    const float* Wk   = (const float*)d_in[5];
    const float* Wv   = (const float*)d_in[6];
    const float* wq_h = (const float*)d_in[7];
    const float* bq_h = (const float*)d_in[8];
    const float* wk_h = (const float*)d_in[9];
    const float* bk_h = (const float*)d_in[10];
    const float* wv_h = (const float*)d_in[11];
    const float* bv_h = (const float*)d_in[12];
    const float* Wo   = (const float*)d_in[13];
    float* out = (float*)d_out;

    cudaFuncSetAttribute(proj_kernel,
                         cudaFuncAttributeMaxDynamicSharedMemorySize, P_SMEM);

    prep0_kernel<<<160, 256>>>(Wo);
    combine_kernel<<<dim3(16, 1, 24), 256>>>(Wq, Wk, Wv, wq_h, wk_h, wv_h);
    wsplit_kernel<<<dim3(128, 4), 256>>>();
    proj_kernel<<<dim3(128, 1, 3), 256, P_SMEM>>>(query, key, value, bq_h, bk_h, bv_h);
    attn_kernel<<<dim3(32, NB, 4), 128>>>();
    merge_kernel<<<NM*32/256, 256>>>();
    outgemm_kernel<<<dim3(128, 16), 256>>>(out);
}

// round 16
// speedup vs baseline: 1.0840x; 1.0840x over previous
#include <cuda_runtime.h>
#include <cuda_bf16.h>
#include <math.h>

// Problem constants
#define NB 4
#define NS 2048
#define ND 1024
#define NHD 64
#define NM (NB*NS)   // 8192

// ---------------- scratch (device globals; no allocation allowed) ----------
__device__ float g_Wqh[ND*NHD];
__device__ float g_Wkh[ND*NHD];
__device__ float g_Wvh[ND*NHD];
__device__ __nv_bfloat16 g_Wqh_hi[ND*NHD], g_Wqh_lo[ND*NHD];
__device__ __nv_bfloat16 g_Wkh_hi[ND*NHD], g_Wkh_lo[ND*NHD];
__device__ __nv_bfloat16 g_Wvh_hi[ND*NHD], g_Wvh_lo[ND*NHD];
__device__ __nv_bfloat16 g_Wo_hi[NHD*ND],  g_Wo_lo[NHD*ND];
__device__ __nv_bfloat16 g_qh_hi[NM*NHD], g_qh_lo[NM*NHD];
__device__ __nv_bfloat16 g_kh_hi[NM*NHD], g_kh_lo[NM*NHD];
__device__ __nv_bfloat16 g_vh_hi[NM*NHD], g_vh_lo[NM*NHD];
__device__ float g_po[4][NM*NHD];
__device__ float g_pm[4][NM];
__device__ float g_pl[4][NM];
__device__ __nv_bfloat16 g_oh_hi[NM*NHD], g_oh_lo[NM*NHD];

// ---------------- helpers ---------------------------------------------------
__device__ __forceinline__ void bf16_split_pack(float x0, float x1,
                                                unsigned &hi, unsigned &lo) {
    __nv_bfloat16 h0 = __float2bfloat16_rn(x0);
    __nv_bfloat16 h1 = __float2bfloat16_rn(x1);
    __nv_bfloat16 l0 = __float2bfloat16_rn(x0 - __bfloat162float(h0));
    __nv_bfloat16 l1 = __float2bfloat16_rn(x1 - __bfloat162float(h1));
    hi = (unsigned)__bfloat16_as_ushort(h0) | ((unsigned)__bfloat16_as_ushort(h1) << 16);
    lo = (unsigned)__bfloat16_as_ushort(l0) | ((unsigned)__bfloat16_as_ushort(l1) << 16);
}
__device__ __forceinline__ void ldsm4(unsigned r[4], unsigned addr) {
    asm volatile("ldmatrix.sync.aligned.m8n8.x4.shared.b16 {%0,%1,%2,%3}, [%4];"
                 : "=r"(r[0]), "=r"(r[1]), "=r"(r[2]), "=r"(r[3]) : "r"(addr));
}
__device__ __forceinline__ void ldsm4t(unsigned r[4], unsigned addr) {
    asm volatile("ldmatrix.sync.aligned.m8n8.x4.trans.shared.b16 {%0,%1,%2,%3}, [%4];"
                 : "=r"(r[0]), "=r"(r[1]), "=r"(r[2]), "=r"(r[3]) : "r"(addr));
}
__device__ __forceinline__ void mma_bf16(float c[4], const unsigned a[4],
                                         unsigned b0, unsigned b1) {
    asm volatile(
        "mma.sync.aligned.m16n8k16.row.col.f32.bf16.bf16.f32 "
        "{%0,%1,%2,%3},{%4,%5,%6,%7},{%8,%9},{%0,%1,%2,%3};"
        : "+f"(c[0]), "+f"(c[1]), "+f"(c[2]), "+f"(c[3])
        : "r"(a[0]), "r"(a[1]), "r"(a[2]), "r"(a[3]), "r"(b0), "r"(b1));
}
__device__ __forceinline__ void cpa16(unsigned dst, const void* src) {
    asm volatile("cp.async.cg.shared.global [%0], [%1], 16;" :: "r"(dst), "l"(src));
}
#define CP_COMMIT asm volatile("cp.async.commit_group;")
#define CP_WAIT0  asm volatile("cp.async.wait_group 0;")
#define CP_WAIT1  asm volatile("cp.async.wait_group 1;")

// ---------------- prep0: zero accumulators + Wo planes directly -------------
// blocks 0..63: Wored row h -> bf16 planes (no f32 round-trip).
// blocks 64..159: zero g_Wqh/Wkh/Wvh.
__global__ void prep0_kernel(const float* __restrict__ Wo) {
    if (blockIdx.x < 64) {
        int h = blockIdx.x;
        #pragma unroll
        for (int t = 0; t < 2; t++) {
            int pe = threadIdx.x + t*256;         // pair index 0..511
            int e = pe*2;
            float s0 = 0.f, s1 = 0.f;
            #pragma unroll
            for (int j = 0; j < 16; j++) {
                const float* r = Wo + (size_t)(j*NHD + h)*ND + e;
                s0 += r[0]; s1 += r[1];
            }
            unsigned hh, ll;
            bf16_split_pack(s0, s1, hh, ll);
            *(unsigned*)(g_Wo_hi + (size_t)h*ND + e) = hh;
            *(unsigned*)(g_Wo_lo + (size_t)h*ND + e) = ll;
        }
    } else {
        int zb = blockIdx.x - 64;
        int base = zb * 2048;
        #pragma unroll
        for (int p = 0; p < 8; p++) {
            int i = base + threadIdx.x + p*256;
            if (i < 65536)        g_Wqh[i] = 0.f;
            else if (i < 131072)  g_Wkh[i - 65536] = 0.f;
            else                  g_Wvh[i - 131072] = 0.f;
        }
    }
}
// split only the 3 combined qkv weight matrices (Wo handled in prep0)
__global__ void wsplit_kernel() {
    int m = blockIdx.y;
    const float* src = (m==0)?g_Wqh:(m==1)?g_Wkh:g_Wvh;
    unsigned* hi = (unsigned*)((m==0)?g_Wqh_hi:(m==1)?g_Wkh_hi:g_Wvh_hi);
    unsigned* lo = (unsigned*)((m==0)?g_Wqh_lo:(m==1)?g_Wkh_lo:g_Wvh_lo);
    int i = blockIdx.x*blockDim.x + threadIdx.x;
    float2 v = *(const float2*)(src + 2*i);
    unsigned h, l;
    bf16_split_pack(v.x, v.y, h, l);
    hi[i] = h; lo[i] = l;
}

// ---------------- combine (R4-exact): Wxh = Wx @ wx_h, split-K(8) atomic ----
#define G_SM_A_HI 0
#define G_SM_A_LO 5120
#define G_SM_B_HI 10240
#define G_SM_B_LO 14848
__global__ void __launch_bounds__(256) combine_kernel(
    const float* __restrict__ Wq, const float* __restrict__ Wk, const float* __restrict__ Wv,
    const float* __restrict__ wqh, const float* __restrict__ wkh, const float* __restrict__ wvh)
{
    int z = blockIdx.z;
    int which = z >> 3, chunk = z & 7;
    const float* A  = (which==0) ? Wq  : (which==1) ? Wk  : Wv;
    const float* Bm = (which==0) ? wqh : (which==1) ? wkh : wvh;
    float*       C  = (which==0) ? g_Wqh : (which==1) ? g_Wkh : g_Wvh;
    int m0 = blockIdx.x*64, kStart = chunk*128;

    __shared__ __align__(16) unsigned char sm[19456];
    unsigned sbase = (unsigned)__cvta_generic_to_shared(sm);
    int tid = threadIdx.x, lane = tid & 31, wid = tid >> 5;
    int wm = wid >> 1, wn = wid & 1;
    int lRow = lane & 15, lHi = (lane >> 4) << 3;

    float c[4][4] = {};
    float4 aReg[2], bReg[2];
    #pragma unroll
    for (int p = 0; p < 2; p++) {
        int idx = tid + p*256;
        aReg[p] = *(const float4*)(A + (size_t)(m0 + (idx>>3))*ND + kStart + (idx&7)*4);
        bReg[p] = *(const float4*)(Bm + (size_t)(kStart + (idx>>4))*NHD + (idx&15)*4);
    }
    for (int kb = 0; kb < 128; kb += 32) {
        #pragma unroll
        for (int p = 0; p < 2; p++) {
            int idx = tid + p*256;
            {   int r = idx>>3, c4 = idx&7;
                unsigned h01,l01,h23,l23;
                bf16_split_pack(aReg[p].x, aReg[p].y, h01, l01);
                bf16_split_pack(aReg[p].z, aReg[p].w, h23, l23);
                *(uint2*)(sm + G_SM_A_HI + r*80 + c4*8) = make_uint2(h01,h23);
                *(uint2*)(sm + G_SM_A_LO + r*80 + c4*8) = make_uint2(l01,l23);
            }
            {   int r = idx>>4, c4 = idx&15;
                unsigned h01,l01,h23,l23;
                bf16_split_pack(bReg[p].x, bReg[p].y, h01, l01);
                bf16_split_pack(bReg[p].z, bReg[p].w, h23, l23);
                *(uint2*)(sm + G_SM_B_HI + r*144 + c4*8) = make_uint2(h01,h23);
                *(uint2*)(sm + G_SM_B_LO + r*144 + c4*8) = make_uint2(l01,l23);
            }
        }
        __syncthreads();
        if (kb + 32 < 128) {
            int k0 = kStart + kb + 32;
            #pragma unroll
            for (int p = 0; p < 2; p++) {
                int idx = tid + p*256;
                aReg[p] = *(const float4*)(A + (size_t)(m0 + (idx>>3))*ND + k0 + (idx&7)*4);
                bReg[p] = *(const float4*)(Bm + (size_t)(k0 + (idx>>4))*NHD + (idx&15)*4);
            }
        }
        #pragma unroll
        for (int ks = 0; ks < 32; ks += 16) {
            unsigned ah[4], al[4], bh[2][4], bl[2][4];
            unsigned offA = sbase + G_SM_A_HI + (unsigned)((wm*16 + lRow)*80 + (ks + lHi)*2);
            ldsm4(ah, offA);
            ldsm4(al, offA + (G_SM_A_LO - G_SM_A_HI));
            #pragma unroll
            for (int np = 0; np < 2; np++) {
                unsigned offB = sbase + G_SM_B_HI + (unsigned)((ks + lRow)*144 + (wn*32 + np*16 + lHi)*2);
                ldsm4t(bh[np], offB);
                ldsm4t(bl[np], offB + (G_SM_B_LO - G_SM_B_HI));
            }
            #pragma unroll
            for (int nt = 0; nt < 4; nt++) {
                unsigned b0h = bh[nt>>1][(nt&1)*2], b1h = bh[nt>>1][(nt&1)*2+1];
                unsigned b0l = bl[nt>>1][(nt&1)*2], b1l = bl[nt>>1][(nt&1)*2+1];
                mma_bf16(c[nt], ah, b0h, b1h);
                mma_bf16(c[nt], ah, b0l, b1l);
                mma_bf16(c[nt], al, b0h, b1h);
            }
        }
        __syncthreads();
    }
    int rowL = m0 + wm*16 + (lane>>2);
    #pragma unroll
    for (int nt = 0; nt < 4; nt++) {
        int col = wn*32 + nt*8 + (lane&3)*2;
        atomicAdd(&C[(size_t)rowL*NHD+col],       c[nt][0]);
        atomicAdd(&C[(size_t)rowL*NHD+col+1],     c[nt][1]);
        atomicAdd(&C[(size_t)(rowL+8)*NHD+col],   c[nt][2]);
        atomicAdd(&C[(size_t)(rowL+8)*NHD+col+1], c[nt][3]);
    }
}

// ---------------- proj v7 (R14-exact): BK=64, 2-stage B ring ----------------
#define P_A_HI 0
#define P_A_LO 9216
#define P_BST(s) (18432 + (s)*18432)
#define P_SMEM  55296
__global__ void __launch_bounds__(256) proj_kernel(
    const float* __restrict__ q, const float* __restrict__ k, const float* __restrict__ v,
    const float* __restrict__ bq, const float* __restrict__ bk, const float* __restrict__ bv)
{
    int which = blockIdx.z;
    const float* A    = (which==0) ? q     : (which==1) ? k     : v;
    const __nv_bfloat16* Whi = (which==0) ? g_Wqh_hi : (which==1) ? g_Wkh_hi : g_Wvh_hi;
    const __nv_bfloat16* Wlo = (which==0) ? g_Wqh_lo : (which==1) ? g_Wkh_lo : g_Wvh_lo;
    const float* bias = (which==0) ? bq    : (which==1) ? bk    : bv;
    __nv_bfloat16* Chi = (which==0) ? g_qh_hi : (which==1) ? g_kh_hi : g_vh_hi;
    __nv_bfloat16* Clo = (which==0) ? g_qh_lo : (which==1) ? g_kh_lo : g_vh_lo;

    extern __shared__ __align__(16) unsigned char sm[];
    unsigned sbase = (unsigned)__cvta_generic_to_shared(sm);
    int tid = threadIdx.x, lane = tid & 31, wid = tid >> 5;
    int wm = wid >> 1, wn = wid & 1;
    int lRow = lane & 15, lHi = (lane >> 4) << 3;
    int m0 = blockIdx.x*64;

    auto cpB = [&](int kt, int slot) {
        #pragma unroll
        for (int p = 0; p < 4; p++) {
            int idx = tid + p*256;
            int pl = idx >> 9, rr = (idx >> 3) & 63, ch = idx & 7;
            const __nv_bfloat16* src = pl ? Wlo : Whi;
            cpa16(sbase + (unsigned)(P_BST(slot) + pl*9216 + rr*144 + ch*16),
                  src + (size_t)(kt*64 + rr)*NHD + ch*8);
        }
    };

    float c[4][4] = {};
    float4 aReg[4];
    cpB(0, 0); CP_COMMIT;
    #pragma unroll
    for (int p = 0; p < 4; p++) {
        int idx = tid + p*256;
        aReg[p] = *(const float4*)(A + (size_t)(m0 + (idx>>4))*ND + (idx&15)*4);
    }

    for (int it = 0; it < 16; it++) {
        int st = it & 1;
        __syncthreads();
        #pragma unroll
        for (int p = 0; p < 4; p++) {
            int idx = tid + p*256;
            int r = idx>>4, ch = idx&15;
            unsigned h01,l01,h23,l23;
            bf16_split_pack(aReg[p].x, aReg[p].y, h01, l01);
            bf16_split_pack(aReg[p].z, aReg[p].w, h23, l23);
            *(uint2*)(sm + P_A_HI + r*144 + ch*8) = make_uint2(h01,h23);
            *(uint2*)(sm + P_A_LO + r*144 + ch*8) = make_uint2(l01,l23);
        }
        bool hasNext = (it + 1 < 16);
        if (hasNext) cpB(it + 1, st^1);
        CP_COMMIT;
        if (hasNext) {
            int k0 = (it + 1) * 64;
            #pragma unroll
            for (int p = 0; p < 4; p++) {
                int idx = tid + p*256;
                aReg[p] = *(const float4*)(A + (size_t)(m0 + (idx>>4))*ND + k0 + (idx&15)*4);
            }
        }
        CP_WAIT1;
        __syncthreads();
        unsigned pb = sbase + (unsigned)P_BST(st);
        #pragma unroll
        for (int ks = 0; ks < 64; ks += 16) {
            unsigned ah[4], al[4], bh[2][4], bl[2][4];
            unsigned offA = sbase + P_A_HI + (unsigned)((wm*16 + lRow)*144 + (ks + lHi)*2);
            ldsm4(ah, offA);
            ldsm4(al, offA + (P_A_LO - P_A_HI));
            #pragma unroll
            for (int np = 0; np < 2; np++) {
                unsigned offB = pb + (unsigned)((ks + lRow)*144 + (wn*32 + np*16 + lHi)*2);
                ldsm4t(bh[np], offB);
                ldsm4t(bl[np], offB + 9216);
            }
            #pragma unroll
            for (int nt = 0; nt < 4; nt++) {
                unsigned b0h = bh[nt>>1][(nt&1)*2], b1h = bh[nt>>1][(nt&1)*2+1];
                unsigned b0l = bl[nt>>1][(nt&1)*2], b1l = bl[nt>>1][(nt&1)*2+1];
                mma_bf16(c[nt], ah, b0h, b1h);
                mma_bf16(c[nt], ah, b0l, b1l);
                mma_bf16(c[nt], al, b0h, b1h);
            }
        }
    }
    int rowL = m0 + wm*16 + (lane>>2);
    #pragma unroll
    for (int nt = 0; nt < 4; nt++) {
        int col = wn*32 + nt*8 + (lane&3)*2;
        float v0 = c[nt][0] + bias[col],   v1 = c[nt][1] + bias[col+1];
        float v2 = c[nt][2] + bias[col],   v3 = c[nt][3] + bias[col+1];
        unsigned h01,l01,h23,l23;
        bf16_split_pack(v0,v1,h01,l01);
        bf16_split_pack(v2,v3,h23,l23);
        *(unsigned*)(Chi + (size_t)rowL*NHD + col)     = h01;
        *(unsigned*)(Clo + (size_t)rowL*NHD + col)     = l01;
        *(unsigned*)(Chi + (size_t)(rowL+8)*NHD + col) = h23;
        *(unsigned*)(Clo + (size_t)(rowL+8)*NHD + col) = l23;
    }
}

// ---------------- attention: BM=64, BN=32, balanced 4-way split-KV (R11) ----
#define AQ_HI 0
#define AQ_LO 8192
#define AST   16384
#define ASTSZ 16384

__device__ __forceinline__ void attn_load_stage(unsigned sbst, size_t kvbase, int tid) {
    #pragma unroll
    for (int p = 0; p < 2; p++) {
        int idx = tid + p*128;
        int r = idx >> 3, c = idx & 7;
        unsigned sw = (unsigned)(r*128 + ((c ^ (r & 7)) << 4));
        size_t g = kvbase + (size_t)r*NHD + c*8;
        cpa16(sbst + 0     + sw, g_kh_hi + g);
        cpa16(sbst + 4096  + sw, g_kh_lo + g);
        cpa16(sbst + 8192  + sw, g_vh_hi + g);
        cpa16(sbst + 12288 + sw, g_vh_lo + g);
    }
}

__global__ void __launch_bounds__(128) attn_kernel() {
    __shared__ __align__(16) unsigned char sm[49152];
    unsigned sb = (unsigned)__cvta_generic_to_shared(sm);
    int tid = threadIdx.x, lane = tid & 31, wid = tid >> 5;
    int qb = blockIdx.x, b = blockIdx.y, split = blockIdx.z;
    size_t base = (size_t)b * NS * NHD;
    int r0 = qb * 64;
    int T = 2*qb + 2;
    int jt0 = (split*T) >> 2;
    int jt1 = ((split+1)*T) >> 2;

    #pragma unroll
    for (int p = 0; p < 4; p++) {
        int idx = tid + p*128;
        int r = idx >> 3, c = idx & 7;
        unsigned sw = (unsigned)(r*128 + ((c ^ (r & 7)) << 4));
        size_t g = base + (size_t)(r0 + r)*NHD + c*8;
        cpa16(sb + AQ_HI + sw, g_qh_hi + g);
        cpa16(sb + AQ_LO + sw, g_qh_lo + g);
    }
    CP_COMMIT;
    if (jt0 < jt1)
        attn_load_stage(sb + AST + (unsigned)((jt0 & 1) * ASTSZ),
                        base + (size_t)jt0*32*NHD, tid);
    CP_COMMIT;
    CP_WAIT1;
    __syncthreads();

    unsigned qh_f[4][4], ql_f[4][4];
    {
        int row = wid*16 + (lane & 15);
        #pragma unroll
        for (int c = 0; c < 4; c++) {
            int ch = 2*c + (lane >> 4);
            unsigned addr = sb + AQ_HI + (unsigned)(row*128 + ((ch ^ (row & 7)) << 4));
            ldsm4(qh_f[c], addr);
            ldsm4(ql_f[c], addr + (AQ_LO - AQ_HI));
        }
    }

    float o[8][4] = {};
    float m0r = -1e30f, m1r = -1e30f, l0r = 0.f, l1r = 0.f;
    const float c1 = 0.125f * 1.4426950408889634f;

    for (int jt = jt0; jt < jt1; jt++) {
        unsigned cur = sb + AST + (unsigned)((jt & 1) * ASTSZ);
        if (jt + 1 < jt1)
            attn_load_stage(sb + AST + (unsigned)(((jt+1) & 1) * ASTSZ),
                            base + (size_t)(jt+1)*32*NHD, tid);
        CP_COMMIT;
        CP_WAIT1;
        __syncthreads();

        float s[4][4] = {};
        #pragma unroll
        for (int c = 0; c < 4; c++) {
            int ch = 2*c + ((lane >> 3) & 1);
            int keyr = ((lane >> 4) << 3) + (lane & 7);
            unsigned a0 = cur + (unsigned)(keyr*128 + ((ch ^ (keyr & 7)) << 4));
            unsigned a1 = a0 + 16*128;
            unsigned kh0[4], kh1[4], kl0[4], kl1[4];
            ldsm4(kh0, a0); ldsm4(kh1, a1);
            ldsm4(kl0, a0 + 4096); ldsm4(kl1, a1 + 4096);
            mma_bf16(s[0], qh_f[c], kh0[0], kh0[1]);
            mma_bf16(s[0], qh_f[c], kl0[0], kl0[1]);
            mma_bf16(s[0], ql_f[c], kh0[0], kh0[1]);
            mma_bf16(s[1], qh_f[c], kh0[2], kh0[3]);
            mma_bf16(s[1], qh_f[c], kl0[2], kl0[3]);
            mma_bf16(s[1], ql_f[c], kh0[2], kh0[3]);
            mma_bf16(s[2], qh_f[c], kh1[0], kh1[1]);
            mma_bf16(s[2], qh_f[c], kl1[0], kl1[1]);
            mma_bf16(s[2], ql_f[c], kh1[0], kh1[1]);
            mma_bf16(s[3], qh_f[c], kh1[2], kh1[3]);
            mma_bf16(s[3], qh_f[c], kl1[2], kl1[3]);
            mma_bf16(s[3], ql_f[c], kh1[2], kh1[3]);
        }

        bool dom = (jt >= 2*qb);
        int rgl = r0 + wid*16 + (lane >> 2);
        #pragma unroll
        for (int f = 0; f < 4; f++) {
            int kg = jt*32 + f*8 + (lane & 3)*2;
            #pragma unroll
            for (int e = 0; e < 4; e++) {
                float t = s[f][e] * c1;
                if (dom && (kg + (e & 1)) > (rgl + ((e >= 2) ? 8 : 0))) t = -1e30f;
                s[f][e] = t;
            }
        }

        float mx0 = -1e30f, mx1 = -1e30f;
        #pragma unroll
        for (int f = 0; f < 4; f++) {
            mx0 = fmaxf(mx0, fmaxf(s[f][0], s[f][1]));
            mx1 = fmaxf(mx1, fmaxf(s[f][2], s[f][3]));
        }
        mx0 = fmaxf(mx0, __shfl_xor_sync(0xffffffffu, mx0, 1));
        mx0 = fmaxf(mx0, __shfl_xor_sync(0xffffffffu, mx0, 2));
        mx1 = fmaxf(mx1, __shfl_xor_sync(0xffffffffu, mx1, 1));
        mx1 = fmaxf(mx1, __shfl_xor_sync(0xffffffffu, mx1, 2));
        float mn0 = fmaxf(m0r, mx0), mn1 = fmaxf(m1r, mx1);
        float al0 = exp2f(m0r - mn0), al1 = exp2f(m1r - mn1);
        m0r = mn0; m1r = mn1;
        float rs0 = 0.f, rs1 = 0.f;
        #pragma unroll
        for (int f = 0; f < 4; f++) {
            s[f][0] = exp2f(s[f][0] - mn0);
            s[f][1] = exp2f(s[f][1] - mn0);
            s[f][2] = exp2f(s[f][2] - mn1);
            s[f][3] = exp2f(s[f][3] - mn1);
            rs0 += s[f][0] + s[f][1];
            rs1 += s[f][2] + s[f][3];
        }
        rs0 += __shfl_xor_sync(0xffffffffu, rs0, 1);
        rs0 += __shfl_xor_sync(0xffffffffu, rs0, 2);
        rs1 += __shfl_xor_sync(0xffffffffu, rs1, 1);
        rs1 += __shfl_xor_sync(0xffffffffu, rs1, 2);
        l0r = l0r*al0 + rs0;
        l1r = l1r*al1 + rs1;
        #pragma unroll
        for (int f = 0; f < 8; f++) {
            o[f][0] *= al0; o[f][1] *= al0;
            o[f][2] *= al1; o[f][3] *= al1;
        }

        #pragma unroll
        for (int ka = 0; ka < 2; ka++) {
            unsigned ph[4], pl[4];
            bf16_split_pack(s[2*ka][0],   s[2*ka][1],   ph[0], pl[0]);
            bf16_split_pack(s[2*ka][2],   s[2*ka][3],   ph[1], pl[1]);
            bf16_split_pack(s[2*ka+1][0], s[2*ka+1][1], ph[2], pl[2]);
            bf16_split_pack(s[2*ka+1][2], s[2*ka+1][3], ph[3], pl[3]);
            #pragma unroll
            for (int fp = 0; fp < 4; fp++) {
                int ch = 2*fp + (lane >> 4);
                int kvr = ka*16 + (lane & 15);
                unsigned av = cur + 8192 + (unsigned)(kvr*128 + ((ch ^ (kvr & 7)) << 4));
                unsigned vh[4], vl[4];
                ldsm4t(vh, av); ldsm4t(vl, av + 4096);
                mma_bf16(o[2*fp],   ph, vh[0], vh[1]);
                mma_bf16(o[2*fp],   pl, vh[0], vh[1]);
                mma_bf16(o[2*fp],   ph, vl[0], vl[1]);
                mma_bf16(o[2*fp+1], ph, vh[2], vh[3]);
                mma_bf16(o[2*fp+1], pl, vh[2], vh[3]);
                mma_bf16(o[2*fp+1], ph, vl[2], vl[3]);
            }
        }
        __syncthreads();
    }

    int rowg = r0 + wid*16 + (lane >> 2);
    size_t rb = (size_t)b*NS + rowg;
    #pragma unroll
    for (int f = 0; f < 8; f++) {
        int hd = f*8 + (lane & 3)*2;
        *(float2*)(g_po[split] + rb*NHD + hd)     = make_float2(o[f][0], o[f][1]);
        *(float2*)(g_po[split] + (rb+8)*NHD + hd) = make_float2(o[f][2], o[f][3]);
    }
    if ((lane & 3) == 0) {
        g_pm[split][rb]   = m0r;  g_pl[split][rb]   = l0r;
        g_pm[split][rb+8] = m1r;  g_pl[split][rb+8] = l1r;
    }
}

// ---------------- merge v2: float4 per thread (4 columns) -------------------
// grid NM*16/256 = 512 blocks; thread handles row = idx>>4, cols (idx&15)*4.
__global__ void merge_kernel() {
    int idx = blockIdx.x*blockDim.x + threadIdx.x;    // 0 .. NM*16-1
    int row = idx >> 4;
    int cp  = (idx & 15)*4;
    float m0 = g_pm[0][row], m1 = g_pm[1][row];
    float m2 = g_pm[2][row], m3 = g_pm[3][row];
    float M = fmaxf(fmaxf(m0, m1), fmaxf(m2, m3));
    float e0 = exp2f(m0 - M), e1 = exp2f(m1 - M);
    float e2 = exp2f(m2 - M), e3 = exp2f(m3 - M);
    float inv = 1.f / (g_pl[0][row]*e0 + g_pl[1][row]*e1
                     + g_pl[2][row]*e2 + g_pl[3][row]*e3);
    float4 a0 = *(const float4*)(g_po[0] + (size_t)row*NHD + cp);
    float4 a1 = *(const float4*)(g_po[1] + (size_t)row*NHD + cp);
    float4 a2 = *(const float4*)(g_po[2] + (size_t)row*NHD + cp);
    float4 a3 = *(const float4*)(g_po[3] + (size_t)row*NHD + cp);
    float x0 = (a0.x*e0 + a1.x*e1 + a2.x*e2 + a3.x*e3)*inv;
    float x1 = (a0.y*e0 + a1.y*e1 + a2.y*e2 + a3.y*e3)*inv;
    float x2 = (a0.z*e0 + a1.z*e1 + a2.z*e2 + a3.z*e3)*inv;
    float x3 = (a0.w*e0 + a1.w*e1 + a2.w*e2 + a3.w*e3)*inv;
    unsigned h01, l01, h23, l23;
    bf16_split_pack(x0, x1, h01, l01);
    bf16_split_pack(x2, x3, h23, l23);
    *(uint2*)(g_oh_hi + (size_t)row*NHD + cp) = make_uint2(h01, h23);
    *(uint2*)(g_oh_lo + (size_t)row*NHD + cp) = make_uint2(l01, l23);
}

// ---------------- outgemm (R4-exact) ----------------------------------------
#define O_A_HI 0
#define O_A_LO 9216
#define O_B_HI 18432
#define O_B_LO 27648
__global__ void __launch_bounds__(256) outgemm_kernel(float* __restrict__ out) {
    __shared__ __align__(16) unsigned char sm[36864];
    unsigned sbase = (unsigned)__cvta_generic_to_shared(sm);
    int tid = threadIdx.x, lane = tid & 31, wid = tid >> 5;
    int wm = wid >> 1, wn = wid & 1;
    int lRow = lane & 15, lHi = (lane >> 4) << 3;
    int m0 = blockIdx.x*64, n0 = blockIdx.y*64;

    #pragma unroll
    for (int p = 0; p < 4; p++) {
        int idx = tid + p*256;
        int pl = (idx >> 9) & 1, r = (idx >> 3) & 63, ch = idx & 7;
        if (idx < 1024) {
            const __nv_bfloat16* srcA = pl ? g_oh_lo : g_oh_hi;
            cpa16(sbase + O_A_HI + pl*9216 + r*144 + ch*16, srcA + (size_t)(m0 + r)*NHD + ch*8);
        }
    }
    #pragma unroll
    for (int p = 0; p < 4; p++) {
        int idx = tid + p*256;
        int pl = (idx >> 9) & 1, r = (idx >> 3) & 63, ch = idx & 7;
        const __nv_bfloat16* srcB = pl ? g_Wo_lo : g_Wo_hi;
        cpa16(sbase + O_B_HI + pl*9216 + r*144 + ch*16, srcB + (size_t)r*ND + n0 + ch*8);
    }
    CP_COMMIT;
    CP_WAIT0;
    __syncthreads();

    float c[4][4] = {};
    #pragma unroll
    for (int ks = 0; ks < 4; ks++) {
        unsigned ah[4], al[4], bh[2][4], bl[2][4];
        unsigned offA = sbase + O_A_HI + (unsigned)((wm*16 + lRow)*144 + (ks*16 + lHi)*2);
        ldsm4(ah, offA);
        ldsm4(al, offA + 9216);
        #pragma unroll
        for (int np = 0; np < 2; np++) {
            unsigned offB = sbase + O_B_HI + (unsigned)((ks*16 + lRow)*144 + (wn*32 + np*16 + lHi)*2);
            ldsm4t(bh[np], offB);
            ldsm4t(bl[np], offB + 9216);
        }
        #pragma unroll
        for (int nt = 0; nt < 4; nt++) {
            unsigned b0h = bh[nt>>1][(nt&1)*2], b1h = bh[nt>>1][(nt&1)*2+1];
            unsigned b0l = bl[nt>>1][(nt&1)*2], b1l = bl[nt>>1][(nt&1)*2+1];
            mma_bf16(c[nt], ah, b0h, b1h);
            mma_bf16(c[nt], ah, b0l, b1l);
            mma_bf16(c[nt], al, b0h, b1h);
        }
    }
    int rowL = m0 + wm*16 + (lane>>2);
    #pragma unroll
    for (int nt = 0; nt < 4; nt++) {
        int col = n0 + wn*32 + nt*8 + (lane&3)*2;
        *(float2*)(out + (size_t)rowL*ND + col)     = make_float2(c[nt][0], c[nt][1]);
        *(float2*)(out + (size_t)(rowL+8)*ND + col) = make_float2(c[nt][2], c[nt][3]);
    }
}

// ---------------- launch ----------------------------------------------------
extern "C" void kernel_launch(void* const* d_in, const int* in_sizes, int n_in,
                              void* d_out, int out_size) {
    const float* query = (const float*)d_in[0];
    const float* key   = (const float*)d_in[1];
    const float* value = (const float*)d_in[2];
    // d_in[3] = mask (causal, reconstructed analytically — unused)
    const float* Wq   = (const float*)d_in[4];
    const float* Wk   = (const float*)d_in[5];
    const float* Wv   = (const float*)d_in[6];
    const float* wq_h = (const float*)d_in[7];
    const float* bq_h = (const float*)d_in[8];
    const float* wk_h = (const float*)d_in[9];
    const float* bk_h = (const float*)d_in[10];
    const float* wv_h = (const float*)d_in[11];
    const float* bv_h = (const float*)d_in[12];
    const float* Wo   = (const float*)d_in[13];
    float* out = (float*)d_out;

    cudaFuncSetAttribute(proj_kernel,
                         cudaFuncAttributeMaxDynamicSharedMemorySize, P_SMEM);

    prep0_kernel<<<160, 256>>>(Wo);
    combine_kernel<<<dim3(16, 1, 24), 256>>>(Wq, Wk, Wv, wq_h, wk_h, wv_h);
    wsplit_kernel<<<dim3(128, 3), 256>>>();
    proj_kernel<<<dim3(128, 1, 3), 256, P_SMEM>>>(query, key, value, bq_h, bk_h, bv_h);
    attn_kernel<<<dim3(32, NB, 4), 128>>>();
    merge_kernel<<<NM*16/256, 256>>>();
    outgemm_kernel<<<dim3(128, 16), 256>>>(out);
}